// round 1
// baseline (speedup 1.0000x reference)
#include <cuda_runtime.h>
#include <math.h>

#define NN 100000
#define NE 3200000
#define DD 64

// ---- scratch (device globals: no allocation allowed) ----
__device__ __align__(16) float g_q[NN*DD];
__device__ __align__(16) float g_k[NN*DD];
__device__ __align__(16) float g_v[NN*DD];
__device__ __align__(16) float g_acc[NN*DD];   // s (+residual), then += agg
__device__ __align__(16) float g_h[NN*DD];     // tanh output / next-layer input
__device__ __align__(16) float g_scores[NE];
__device__ float g_m[NN];
__device__ float g_sum[NN];
__device__ float g_q3[NN*3];
__device__ float g_k3[NN*3];
__device__ float g_v3[NN*3];

__device__ __forceinline__ void atomicMaxF(float* addr, float val){
    if (val >= 0.0f) atomicMax((int*)addr, __float_as_int(val));
    else             atomicMin((unsigned int*)addr, __float_as_uint(val));
}

// ---------------- GEMM: Y[N,64] = X[N,64] @ W[64,64] + b ----------------
// grid.y = 0..3 selects q/k/v/s. 128-row tiles, 8x4 micro-tile per thread.
__global__ void __launch_bounds__(256) gemm64(
    const float* __restrict__ X,
    const float* __restrict__ Wq, const float* __restrict__ bq,
    const float* __restrict__ Wk, const float* __restrict__ bk,
    const float* __restrict__ Wv, const float* __restrict__ bv,
    const float* __restrict__ Ws, const float* __restrict__ bs,
    int n, int residual)
{
    __shared__ float Xs[128*64];   // 32KB
    __shared__ float Wsh[64*64];   // 16KB  (total exactly 48KB)

    const float* W; const float* bias; float* Y;
    int which = blockIdx.y;
    if      (which==0){W=Wq; bias=bq; Y=g_q;}
    else if (which==1){W=Wk; bias=bk; Y=g_k;}
    else if (which==2){W=Wv; bias=bv; Y=g_v;}
    else              {W=Ws; bias=bs; Y=g_acc;}

    int t  = threadIdx.x;
    int r0 = blockIdx.x*128;

    #pragma unroll
    for (int i=0;i<4;i++){
        int idx = t + i*256;                       // 1024 float4s of W
        ((float4*)Wsh)[idx] = ((const float4*)W)[idx];
    }
    #pragma unroll
    for (int i=0;i<8;i++){
        int idx = t + i*256;                       // 2048 float4s of X tile
        int row = idx >> 4;
        int c4  = idx & 15;
        float4 val = make_float4(0.f,0.f,0.f,0.f);
        if (r0+row < n) val = ((const float4*)X)[(size_t)(r0+row)*16 + c4];
        ((float4*)Xs)[row*16 + c4] = val;
    }
    __syncthreads();

    int tx = t & 15;    // cols tx*4 .. tx*4+3
    int ty = t >> 4;    // rows ty*8 .. ty*8+7
    float acc[8][4];
    #pragma unroll
    for (int i=0;i<8;i++){
        #pragma unroll
        for (int j=0;j<4;j++) acc[i][j]=0.f;
    }

    #pragma unroll 8
    for (int k=0;k<64;k++){
        float4 b4 = *((float4*)&Wsh[k*64 + tx*4]);
        float a[8];
        #pragma unroll
        for (int i=0;i<8;i++) a[i] = Xs[(ty*8+i)*64 + k];
        #pragma unroll
        for (int i=0;i<8;i++){
            acc[i][0] += a[i]*b4.x;
            acc[i][1] += a[i]*b4.y;
            acc[i][2] += a[i]*b4.z;
            acc[i][3] += a[i]*b4.w;
        }
    }

    float4 bb = ((const float4*)bias)[tx];
    #pragma unroll
    for (int i=0;i<8;i++){
        int row = ty*8+i;
        if (r0+row < n){
            float4 o;
            o.x = acc[i][0]+bb.x; o.y = acc[i][1]+bb.y;
            o.z = acc[i][2]+bb.z; o.w = acc[i][3]+bb.w;
            if (which==3 && residual){
                o.x += Xs[row*64 + tx*4+0];
                o.y += Xs[row*64 + tx*4+1];
                o.z += Xs[row*64 + tx*4+2];
                o.w += Xs[row*64 + tx*4+3];
            }
            ((float4*)Y)[(size_t)(r0+row)*16 + tx] = o;
        }
    }
}

// ---------------- per-node init ----------------
__global__ void init_nodes(){
    int i = blockIdx.x*blockDim.x + threadIdx.x;
    if (i < NN){
        g_m[i]   = __int_as_float(0xff800000u);  // -inf
        g_sum[i] = 0.f;
    }
}

// ---------------- edge scores (D=64): 16 lanes per edge ----------------
__global__ void __launch_bounds__(256) scores64(const int* __restrict__ ei){
    long long gt = (long long)blockIdx.x*blockDim.x + threadIdx.x;
    int e = (int)(gt >> 4);
    if (e >= NE) return;
    int lane = threadIdx.x & 15;
    int s = ei[e];
    int d = ei[NE + e];
    float4 qv = ((const float4*)g_q)[(size_t)d*16 + lane];
    float4 kv = ((const float4*)g_k)[(size_t)s*16 + lane];
    float p = qv.x*kv.x + qv.y*kv.y + qv.z*kv.z + qv.w*kv.w;
    p += __shfl_xor_sync(0xffffffffu, p, 8);
    p += __shfl_xor_sync(0xffffffffu, p, 4);
    p += __shfl_xor_sync(0xffffffffu, p, 2);
    p += __shfl_xor_sync(0xffffffffu, p, 1);
    if (lane == 0){
        float sc = p * 0.125f;             // / sqrt(64)
        g_scores[e] = sc;
        atomicMaxF(&g_m[d], sc);
    }
}

// ---------------- exp + segment sum (shared by all layers) ----------------
__global__ void __launch_bounds__(256) expnorm(const int* __restrict__ ei){
    int e = blockIdx.x*blockDim.x + threadIdx.x;
    if (e >= NE) return;
    int d = ei[NE + e];
    float ex = __expf(g_scores[e] - g_m[d]);
    g_scores[e] = ex;
    atomicAdd(&g_sum[d], ex);
}

// ---------------- weighted aggregation (D=64): vector red ----------------
__global__ void __launch_bounds__(256) agg64(const int* __restrict__ ei){
    long long gt = (long long)blockIdx.x*blockDim.x + threadIdx.x;
    int e = (int)(gt >> 4);
    if (e >= NE) return;
    int lane = threadIdx.x & 15;
    int s = ei[e];
    int d = ei[NE + e];
    float w = g_scores[e] / (g_sum[d] + 1e-16f);
    float4 vv = ((const float4*)g_v)[(size_t)s*16 + lane];
    float* dst = &g_acc[(size_t)d*64 + lane*4];
    asm volatile("red.global.add.v4.f32 [%0], {%1,%2,%3,%4};"
        :: "l"(dst), "f"(vv.x*w), "f"(vv.y*w), "f"(vv.z*w), "f"(vv.w*w)
        : "memory");
}

// ---------------- tanh activation ----------------
__global__ void tanh_k(int total){
    int i = blockIdx.x*blockDim.x + threadIdx.x;
    if (i < total) g_h[i] = tanhf(g_acc[i]);
}

// ---------------- layer 3: small GEMM (64 -> 3 x4) + output init ----------------
__global__ void __launch_bounds__(256) gemm3(
    const float* __restrict__ X,
    const float* __restrict__ Wq, const float* __restrict__ bq,
    const float* __restrict__ Wk, const float* __restrict__ bk,
    const float* __restrict__ Wv, const float* __restrict__ bv,
    const float* __restrict__ Ws, const float* __restrict__ bs,
    const float* __restrict__ noise, float* __restrict__ out, int n)
{
    __shared__ float w[64*12];
    __shared__ float bias[12];
    int t = threadIdx.x;
    if (t < 192){
        int kk = t/3, j = t%3;
        w[kk*12 + 0 + j] = Wq[t];
        w[kk*12 + 3 + j] = Wk[t];
        w[kk*12 + 6 + j] = Wv[t];
        w[kk*12 + 9 + j] = Ws[t];
    }
    if (t < 3){
        bias[t]   = bq[t];
        bias[3+t] = bk[t];
        bias[6+t] = bv[t];
        bias[9+t] = bs[t];
    }
    __syncthreads();
    int node = blockIdx.x*256 + t;
    if (node >= n) return;
    float acc[12];
    #pragma unroll
    for (int j=0;j<12;j++) acc[j]=0.f;
    #pragma unroll
    for (int kk=0;kk<16;kk++){
        float4 xv = ((const float4*)X)[(size_t)node*16 + kk];
        #pragma unroll
        for (int j=0;j<12;j++){
            acc[j] += xv.x * w[(kk*4+0)*12+j]
                    + xv.y * w[(kk*4+1)*12+j]
                    + xv.z * w[(kk*4+2)*12+j]
                    + xv.w * w[(kk*4+3)*12+j];
        }
    }
    #pragma unroll
    for (int j=0;j<3;j++){
        g_q3[node*3+j] = acc[j]   + bias[j];
        g_k3[node*3+j] = acc[3+j] + bias[3+j];
        g_v3[node*3+j] = acc[6+j] + bias[6+j];
        // out init = skip term + noise*sigma/SQRT_D = s3 + 0.1*noise
        out[node*3+j]  = acc[9+j] + bias[9+j] + 0.1f*noise[node*3+j];
    }
}

__global__ void __launch_bounds__(256) scores3(const int* __restrict__ ei){
    int e = blockIdx.x*blockDim.x + threadIdx.x;
    if (e >= NE) return;
    int s = ei[e];
    int d = ei[NE + e];
    float p = g_q3[d*3+0]*g_k3[s*3+0]
            + g_q3[d*3+1]*g_k3[s*3+1]
            + g_q3[d*3+2]*g_k3[s*3+2];
    p *= 0.57735026919f;               // 1/sqrt(3)
    g_scores[e] = p;
    atomicMaxF(&g_m[d], p);
}

__global__ void __launch_bounds__(256) agg3(const int* __restrict__ ei,
                                            float* __restrict__ out){
    int e = blockIdx.x*blockDim.x + threadIdx.x;
    if (e >= NE) return;
    int s = ei[e];
    int d = ei[NE + e];
    float w_ = g_scores[e] / (g_sum[d] + 1e-16f);
    #pragma unroll
    for (int j=0;j<3;j++)
        atomicAdd(&out[d*3+j], g_v3[s*3+j]*w_);
}

// ---------------- launcher ----------------
extern "C" void kernel_launch(void* const* d_in, const int* in_sizes, int n_in,
                              void* d_out, int out_size)
{
    const float* x     = (const float*)d_in[0];
    const int*   ei    = (const int*)d_in[1];
    const float* noise = (const float*)d_in[2];
    const float* p[24];
    for (int i=0;i<24;i++) p[i] = (const float*)d_in[3+i];
    float* out = (float*)d_out;

    float* hptr = nullptr;
    cudaGetSymbolAddress((void**)&hptr, g_h);

    dim3 gg((NN+127)/128, 4);
    int eb16 = (int)(((long long)NE*16 + 255)/256);
    int eb1  = (NE + 255)/256;
    int nb   = (NN + 255)/256;
    int nbD  = (NN*DD + 255)/256;

    // ---- layer 1 ----
    gemm64<<<gg,256>>>(x, p[0],p[1],p[2],p[3],p[4],p[5],p[6],p[7], NN, 0);
    init_nodes<<<nb,256>>>();
    scores64<<<eb16,256>>>(ei);
    expnorm<<<eb1,256>>>(ei);
    agg64<<<eb16,256>>>(ei);
    tanh_k<<<nbD,256>>>(NN*DD);

    // ---- layer 2 (with residual into skip output) ----
    gemm64<<<gg,256>>>(hptr, p[8],p[9],p[10],p[11],p[12],p[13],p[14],p[15], NN, 1);
    init_nodes<<<nb,256>>>();
    scores64<<<eb16,256>>>(ei);
    expnorm<<<eb1,256>>>(ei);
    agg64<<<eb16,256>>>(ei);
    tanh_k<<<nbD,256>>>(NN*DD);

    // ---- layer 3 (C=3) ----
    gemm3<<<nb,256>>>(hptr, p[16],p[17],p[18],p[19],p[20],p[21],p[22],p[23],
                      noise, out, NN);
    init_nodes<<<nb,256>>>();
    scores3<<<eb1,256>>>(ei);
    expnorm<<<eb1,256>>>(ei);
    agg3<<<eb1,256>>>(ei, out);
}

// round 3
// speedup vs baseline: 1.9753x; 1.9753x over previous
#include <cuda_runtime.h>
#include <math.h>

#define NN 100000
#define NE 3200000

// ---------------- scratch (device globals) ----------------
__device__ __align__(16) float g_q[NN*64];
__device__ __align__(16) float g_k[NN*64];
__device__ __align__(16) float g_v[NN*64];
__device__ __align__(16) float g_s[NN*64];   // skip (x@Ws+b [+residual])
__device__ __align__(16) float g_h[NN*64];   // layer output
__device__ __align__(16) float g_q3[NN*4];
__device__ __align__(16) float g_k3[NN*4];
__device__ __align__(16) float g_v3[NN*4];
__device__ __align__(16) float g_s3[NN*4];   // skip3 + 0.1*noise
__device__ int g_deg[NN];
__device__ int g_ptr[NN+1];
__device__ int g_cur[NN];
__device__ int g_esrc[NE];

// ---------------- CSR build ----------------
__global__ void zero_deg(){
    int i = blockIdx.x*blockDim.x + threadIdx.x;
    if (i < NN) g_deg[i] = 0;
}
__global__ void hist_k(const int* __restrict__ ei){
    int i = blockIdx.x*blockDim.x + threadIdx.x;
    if (i < NE) atomicAdd(&g_deg[ei[NE + i]], 1);
}
__global__ void __launch_bounds__(1024) scan_k(){
    __shared__ int sh[1024];
    int t = threadIdx.x;
    int carry = 0;
    for (int base = 0; base < NN; base += 4096){
        int v[4]; int s = 0;
        #pragma unroll
        for (int j = 0; j < 4; j++){
            int idx = base + t*4 + j;
            v[j] = (idx < NN) ? g_deg[idx] : 0;
            s += v[j];
        }
        sh[t] = s; __syncthreads();
        #pragma unroll
        for (int off = 1; off < 1024; off <<= 1){
            int x = (t >= off) ? sh[t-off] : 0;
            __syncthreads();
            sh[t] += x;
            __syncthreads();
        }
        int total = sh[1023];
        int excl = carry + sh[t] - s;
        #pragma unroll
        for (int j = 0; j < 4; j++){
            int idx = base + t*4 + j;
            if (idx < NN){ g_ptr[idx] = excl; g_cur[idx] = excl; }
            excl += v[j];
        }
        carry += total;
        __syncthreads();
    }
    if (t == 0) g_ptr[NN] = carry;
}
__global__ void scatter_k(const int* __restrict__ ei){
    int i = blockIdx.x*blockDim.x + threadIdx.x;
    if (i < NE){
        int d = ei[NE + i];
        int p = atomicAdd(&g_cur[d], 1);
        g_esrc[p] = ei[i];
    }
}

// ---------------- fused dual GEMM: Y[N,64] = X@W + b for two W's ----------
// blockIdx.y==0 -> (Wq->g_q, Wk->g_k); blockIdx.y==1 -> (Wv->g_v, Ws->g_s)
// 64-row x 128-col tile, 128 threads, 8x8 micro-tile via fma.rn.f32x2.
__global__ void __launch_bounds__(128) gemm4(
    const float* __restrict__ X,
    const float* __restrict__ Wq, const float* __restrict__ bq,
    const float* __restrict__ Wk, const float* __restrict__ bk,
    const float* __restrict__ Wv, const float* __restrict__ bv,
    const float* __restrict__ Ws, const float* __restrict__ bs,
    int n, int addres)
{
    __shared__ float Xs[64*64];    // transposed + swizzled: [k][row^((k&7)*8)]
    __shared__ float Wsh[64*128];  // [k][c] c: 0..63 first mat, 64..127 second

    const float* WA; const float* WB; const float* bA; const float* bB;
    float* YA; float* YB;
    if (blockIdx.y == 0){ WA=Wq; bA=bq; YA=g_q; WB=Wk; bB=bk; YB=g_k; }
    else                { WA=Wv; bA=bv; YA=g_v; WB=Ws; bB=bs; YB=g_s; }

    int t  = threadIdx.x;
    int r0 = blockIdx.x*64;

    #pragma unroll
    for (int i = 0; i < 16; i++){
        int idx = t + i*128;            // 2048 float4 of weights
        int k = idx >> 5, c4 = idx & 31;
        float4 w = (c4 < 16) ? ((const float4*)WA)[k*16 + c4]
                             : ((const float4*)WB)[k*16 + (c4-16)];
        ((float4*)Wsh)[k*32 + c4] = w;
    }
    #pragma unroll
    for (int i = 0; i < 8; i++){
        int idx = t + i*128;            // 1024 float4 of X tile
        int row = idx >> 4, c4 = idx & 15;
        float4 xv = make_float4(0.f,0.f,0.f,0.f);
        if (r0 + row < n) xv = ((const float4*)X)[(size_t)(r0+row)*16 + c4];
        int k0 = c4*4;
        Xs[(k0+0)*64 + (row ^ (((k0+0)&7)*8))] = xv.x;
        Xs[(k0+1)*64 + (row ^ (((k0+1)&7)*8))] = xv.y;
        Xs[(k0+2)*64 + (row ^ (((k0+2)&7)*8))] = xv.z;
        Xs[(k0+3)*64 + (row ^ (((k0+3)&7)*8))] = xv.w;
    }
    __syncthreads();

    int tx = t & 15, ty = t >> 4;
    int cx = tx*8, ry = ty*8;

    unsigned long long acc[8][4];
    #pragma unroll
    for (int r = 0; r < 8; r++)
        #pragma unroll
        for (int c = 0; c < 4; c++) acc[r][c] = 0ull;

    #pragma unroll 8
    for (int k = 0; k < 64; k++){
        int sw = (k & 7)*8;
        const float* ap = &Xs[k*64 + (ry ^ sw)];
        float4 a0 = *(const float4*)ap;
        float4 a1 = *(const float4*)(ap + 4);
        ulonglong2 b01 = *(const ulonglong2*)&Wsh[k*128 + cx];
        ulonglong2 b23 = *(const ulonglong2*)&Wsh[k*128 + cx + 4];
        unsigned long long bp0 = b01.x, bp1 = b01.y, bp2 = b23.x, bp3 = b23.y;
        float av[8] = {a0.x,a0.y,a0.z,a0.w,a1.x,a1.y,a1.z,a1.w};
        #pragma unroll
        for (int r = 0; r < 8; r++){
            unsigned long long ap2;
            asm("mov.b64 %0, {%1,%1};" : "=l"(ap2) : "f"(av[r]));
            asm("fma.rn.f32x2 %0, %1, %2, %0;" : "+l"(acc[r][0]) : "l"(ap2), "l"(bp0));
            asm("fma.rn.f32x2 %0, %1, %2, %0;" : "+l"(acc[r][1]) : "l"(ap2), "l"(bp1));
            asm("fma.rn.f32x2 %0, %1, %2, %0;" : "+l"(acc[r][2]) : "l"(ap2), "l"(bp2));
            asm("fma.rn.f32x2 %0, %1, %2, %0;" : "+l"(acc[r][3]) : "l"(ap2), "l"(bp3));
        }
    }

    float* Y; const float* bias; int cc;
    if (cx < 64){ Y = YA; bias = bA; cc = cx; }
    else        { Y = YB; bias = bB; cc = cx - 64; }
    float bv8[8];
    #pragma unroll
    for (int j = 0; j < 8; j++) bv8[j] = bias[cc + j];
    // Residual applies ONLY to the skip output (g_s): second matrix of the
    // blockIdx.y==1 pair. (Round-2 bug: missing blockIdx.y check added h to k.)
    bool res = (addres != 0) && (blockIdx.y == 1) && (cx >= 64);

    #pragma unroll
    for (int r = 0; r < 8; r++){
        int row = ry + r;
        if (r0 + row >= n) continue;
        float o[8];
        #pragma unroll
        for (int c = 0; c < 4; c++){
            float lo, hi;
            asm("mov.b64 {%0,%1}, %2;" : "=f"(lo), "=f"(hi) : "l"(acc[r][c]));
            o[2*c]   = lo + bv8[2*c];
            o[2*c+1] = hi + bv8[2*c+1];
        }
        if (res){
            #pragma unroll
            for (int j = 0; j < 8; j++){
                int c = cc + j;
                o[j] += Xs[c*64 + (row ^ ((c & 7)*8))];
            }
        }
        float4 o0 = make_float4(o[0],o[1],o[2],o[3]);
        float4 o1 = make_float4(o[4],o[5],o[6],o[7]);
        ((float4*)Y)[(size_t)(r0+row)*16 + (cc>>2)]     = o0;
        ((float4*)Y)[(size_t)(r0+row)*16 + (cc>>2) + 1] = o1;
    }
}

// ------- fused per-node attention (scores+exp+sum+agg+skip+tanh), D=64 -----
// 16 lanes per node; 2 nodes per warp; 16 nodes per block of 256.
__global__ void __launch_bounds__(256) edge64(){
    int gid = blockIdx.x*16 + (threadIdx.x >> 4);
    if (gid >= NN) return;
    int lane = threadIdx.x & 15;
    unsigned gmask = 0xffffu << (threadIdx.x & 16);

    float4 q = ((const float4*)g_q)[(size_t)gid*16 + lane];
    int beg = g_ptr[gid], end = g_ptr[gid+1];

    float4 acc = make_float4(0.f,0.f,0.f,0.f);
    float ssum = 0.f;
    int i = beg;
    for (; i + 2 <= end; i += 2){
        int s0 = g_esrc[i], s1 = g_esrc[i+1];
        float4 k0 = ((const float4*)g_k)[(size_t)s0*16 + lane];
        float4 k1 = ((const float4*)g_k)[(size_t)s1*16 + lane];
        float4 v0 = ((const float4*)g_v)[(size_t)s0*16 + lane];
        float4 v1 = ((const float4*)g_v)[(size_t)s1*16 + lane];
        float d0 = q.x*k0.x + q.y*k0.y + q.z*k0.z + q.w*k0.w;
        float d1 = q.x*k1.x + q.y*k1.y + q.z*k1.z + q.w*k1.w;
        #pragma unroll
        for (int o = 8; o >= 1; o >>= 1){
            d0 += __shfl_xor_sync(gmask, d0, o);
            d1 += __shfl_xor_sync(gmask, d1, o);
        }
        float e0 = __expf(d0*0.125f);
        float e1 = __expf(d1*0.125f);
        ssum += e0 + e1;
        acc.x += e0*v0.x + e1*v1.x;
        acc.y += e0*v0.y + e1*v1.y;
        acc.z += e0*v0.z + e1*v1.z;
        acc.w += e0*v0.w + e1*v1.w;
    }
    if (i < end){
        int s0 = g_esrc[i];
        float4 k0 = ((const float4*)g_k)[(size_t)s0*16 + lane];
        float4 v0 = ((const float4*)g_v)[(size_t)s0*16 + lane];
        float d0 = q.x*k0.x + q.y*k0.y + q.z*k0.z + q.w*k0.w;
        #pragma unroll
        for (int o = 8; o >= 1; o >>= 1)
            d0 += __shfl_xor_sync(gmask, d0, o);
        float e0 = __expf(d0*0.125f);
        ssum += e0;
        acc.x += e0*v0.x; acc.y += e0*v0.y; acc.z += e0*v0.z; acc.w += e0*v0.w;
    }
    float inv = 1.0f / (ssum + 1e-16f);
    float4 sk = ((const float4*)g_s)[(size_t)gid*16 + lane];
    float4 o;
    o.x = tanhf(acc.x*inv + sk.x);
    o.y = tanhf(acc.y*inv + sk.y);
    o.z = tanhf(acc.z*inv + sk.z);
    o.w = tanhf(acc.w*inv + sk.w);
    ((float4*)g_h)[(size_t)gid*16 + lane] = o;
}

// ---------------- layer 3: 64 -> (3 x 4) GEMM, padded outputs ----------------
__global__ void __launch_bounds__(256) gemm3(
    const float* __restrict__ X,
    const float* __restrict__ Wq, const float* __restrict__ bq,
    const float* __restrict__ Wk, const float* __restrict__ bk,
    const float* __restrict__ Wv, const float* __restrict__ bv,
    const float* __restrict__ Ws, const float* __restrict__ bs,
    const float* __restrict__ noise, int n)
{
    __shared__ float w[64*12];
    __shared__ float bias[12];
    int t = threadIdx.x;
    if (t < 192){
        int kk = t/3, j = t%3;
        w[kk*12 + 0 + j] = Wq[t];
        w[kk*12 + 3 + j] = Wk[t];
        w[kk*12 + 6 + j] = Wv[t];
        w[kk*12 + 9 + j] = Ws[t];
    }
    if (t < 3){
        bias[t]   = bq[t];
        bias[3+t] = bk[t];
        bias[6+t] = bv[t];
        bias[9+t] = bs[t];
    }
    __syncthreads();
    int node = blockIdx.x*256 + t;
    if (node >= n) return;
    float acc[12];
    #pragma unroll
    for (int j = 0; j < 12; j++) acc[j] = 0.f;
    #pragma unroll
    for (int kk = 0; kk < 16; kk++){
        float4 xv = ((const float4*)X)[(size_t)node*16 + kk];
        #pragma unroll
        for (int j = 0; j < 12; j++){
            acc[j] += xv.x * w[(kk*4+0)*12+j]
                    + xv.y * w[(kk*4+1)*12+j]
                    + xv.z * w[(kk*4+2)*12+j]
                    + xv.w * w[(kk*4+3)*12+j];
        }
    }
    float4 q3 = make_float4(acc[0]+bias[0],  acc[1]+bias[1],  acc[2]+bias[2],  0.f);
    float4 k3 = make_float4(acc[3]+bias[3],  acc[4]+bias[4],  acc[5]+bias[5],  0.f);
    float4 v3 = make_float4(acc[6]+bias[6],  acc[7]+bias[7],  acc[8]+bias[8],  0.f);
    float4 s3 = make_float4(acc[9]+bias[9]   + 0.1f*noise[node*3+0],
                            acc[10]+bias[10] + 0.1f*noise[node*3+1],
                            acc[11]+bias[11] + 0.1f*noise[node*3+2], 0.f);
    ((float4*)g_q3)[node] = q3;
    ((float4*)g_k3)[node] = k3;
    ((float4*)g_v3)[node] = v3;
    ((float4*)g_s3)[node] = s3;
}

// ------- layer-3 fused per-node attention (C=3), thread per node -------
__global__ void __launch_bounds__(256) edge3(float* __restrict__ out){
    int node = blockIdx.x*256 + threadIdx.x;
    if (node >= NN) return;
    float4 q = ((const float4*)g_q3)[node];
    int beg = g_ptr[node], end = g_ptr[node+1];
    float sum = 0.f, ax = 0.f, ay = 0.f, az = 0.f;
    int i = beg;
    for (; i + 2 <= end; i += 2){
        int s0 = g_esrc[i], s1 = g_esrc[i+1];
        float4 k0 = ((const float4*)g_k3)[s0];
        float4 k1 = ((const float4*)g_k3)[s1];
        float4 v0 = ((const float4*)g_v3)[s0];
        float4 v1 = ((const float4*)g_v3)[s1];
        float e0 = __expf((q.x*k0.x + q.y*k0.y + q.z*k0.z)*0.57735026919f);
        float e1 = __expf((q.x*k1.x + q.y*k1.y + q.z*k1.z)*0.57735026919f);
        sum += e0 + e1;
        ax += e0*v0.x + e1*v1.x;
        ay += e0*v0.y + e1*v1.y;
        az += e0*v0.z + e1*v1.z;
    }
    if (i < end){
        int s0 = g_esrc[i];
        float4 k0 = ((const float4*)g_k3)[s0];
        float4 v0 = ((const float4*)g_v3)[s0];
        float e0 = __expf((q.x*k0.x + q.y*k0.y + q.z*k0.z)*0.57735026919f);
        sum += e0;
        ax += e0*v0.x; ay += e0*v0.y; az += e0*v0.z;
    }
    float inv = 1.0f / (sum + 1e-16f);
    float4 s3 = ((const float4*)g_s3)[node];
    out[node*3+0] = ax*inv + s3.x;
    out[node*3+1] = ay*inv + s3.y;
    out[node*3+2] = az*inv + s3.z;
}

// ---------------- launcher ----------------
extern "C" void kernel_launch(void* const* d_in, const int* in_sizes, int n_in,
                              void* d_out, int out_size)
{
    const float* x     = (const float*)d_in[0];
    const int*   ei    = (const int*)d_in[1];
    const float* noise = (const float*)d_in[2];
    const float* p[24];
    for (int i = 0; i < 24; i++) p[i] = (const float*)d_in[3+i];
    float* out = (float*)d_out;

    float* hptr = nullptr;
    cudaGetSymbolAddress((void**)&hptr, g_h);

    int eb = (NE + 255)/256;
    int nb = (NN + 255)/256;
    dim3 gg((NN + 63)/64, 2);
    int ng = (NN + 15)/16;

    // CSR build (reused by all layers)
    zero_deg<<<nb,256>>>();
    hist_k<<<eb,256>>>(ei);
    scan_k<<<1,1024>>>();
    scatter_k<<<eb,256>>>(ei);

    // layer 1
    gemm4<<<gg,128>>>(x, p[0],p[1],p[2],p[3],p[4],p[5],p[6],p[7], NN, 0);
    edge64<<<ng,256>>>();

    // layer 2 (residual folded into skip output)
    gemm4<<<gg,128>>>(hptr, p[8],p[9],p[10],p[11],p[12],p[13],p[14],p[15], NN, 1);
    edge64<<<ng,256>>>();

    // layer 3
    gemm3<<<nb,256>>>(hptr, p[16],p[17],p[18],p[19],p[20],p[21],p[22],p[23],
                      noise, NN);
    edge3<<<nb,256>>>(out);
}

// round 4
// speedup vs baseline: 2.2621x; 1.1452x over previous
#include <cuda_runtime.h>
#include <cuda_fp16.h>
#include <math.h>

#define NN 100000
#define NE 3200000

// ---------------- scratch (device globals) ----------------
__device__ __align__(16) float  g_q [NN*64];
__device__ __align__(16) __half g_kh[NN*64];
__device__ __align__(16) __half g_vh[NN*64];
__device__ __align__(16) float  g_s [NN*64];   // skip (x@Ws+b [+residual])
__device__ __align__(16) float  g_h [NN*64];   // layer output
__device__ __align__(16) float  g_q3 [NN*4];
__device__ __align__(16) float  g_s3 [NN*4];   // skip3 + 0.1*noise
__device__ __align__(32) float  g_kv3[NN*8];   // {k3.xyz, v3.xyz, pad2} per node
__device__ int g_deg[NN];
__device__ int g_ptr[NN+1];
__device__ int g_cur[NN];
__device__ int g_esrc[NE];

// ---------------- CSR build ----------------
__global__ void hist_k(const int* __restrict__ ei){
    int i = blockIdx.x*blockDim.x + threadIdx.x;   // NE/4 threads
    if (i < NE/4){
        int4 d = ((const int4*)(ei + NE))[i];
        atomicAdd(&g_deg[d.x], 1);
        atomicAdd(&g_deg[d.y], 1);
        atomicAdd(&g_deg[d.z], 1);
        atomicAdd(&g_deg[d.w], 1);
    }
}
__global__ void __launch_bounds__(1024) scan_k(){
    __shared__ int sh[1024];
    int t = threadIdx.x;
    int carry = 0;
    for (int base = 0; base < NN; base += 4096){
        int v[4]; int s = 0;
        #pragma unroll
        for (int j = 0; j < 4; j++){
            int idx = base + t*4 + j;
            v[j] = (idx < NN) ? g_deg[idx] : 0;
            s += v[j];
        }
        sh[t] = s; __syncthreads();
        #pragma unroll
        for (int off = 1; off < 1024; off <<= 1){
            int x = (t >= off) ? sh[t-off] : 0;
            __syncthreads();
            sh[t] += x;
            __syncthreads();
        }
        int total = sh[1023];
        int excl = carry + sh[t] - s;
        #pragma unroll
        for (int j = 0; j < 4; j++){
            int idx = base + t*4 + j;
            if (idx < NN){ g_ptr[idx] = excl; g_cur[idx] = excl; }
            excl += v[j];
        }
        carry += total;
        __syncthreads();
    }
    if (t == 0) g_ptr[NN] = carry;
}
__global__ void scatter_k(const int* __restrict__ ei){
    int i = blockIdx.x*blockDim.x + threadIdx.x;   // NE/4 threads
    if (i < NE/4){
        int4 s = ((const int4*)ei)[i];
        int4 d = ((const int4*)(ei + NE))[i];
        g_esrc[atomicAdd(&g_cur[d.x], 1)] = s.x;
        g_esrc[atomicAdd(&g_cur[d.y], 1)] = s.y;
        g_esrc[atomicAdd(&g_cur[d.z], 1)] = s.z;
        g_esrc[atomicAdd(&g_cur[d.w], 1)] = s.w;
    }
}

// ---------------- fused dual GEMM: Y[N,64] = X@W + b for two W's ----------
// blockIdx.y==0 -> (Wq->g_q fp32, Wk->g_kh half)
// blockIdx.y==1 -> (Wv->g_vh half, Ws->g_s fp32)
__global__ void __launch_bounds__(128) gemm4(
    const float* __restrict__ X,
    const float* __restrict__ Wq, const float* __restrict__ bq,
    const float* __restrict__ Wk, const float* __restrict__ bk,
    const float* __restrict__ Wv, const float* __restrict__ bv,
    const float* __restrict__ Ws, const float* __restrict__ bs,
    int n, int addres)
{
    __shared__ float Xs[64*64];    // transposed + swizzled: [k][row^((k&7)*8)]
    __shared__ float Wsh[64*128];  // [k][c] c: 0..63 first mat, 64..127 second

    const float* WA; const float* WB; const float* bA; const float* bB;
    if (blockIdx.y == 0){ WA=Wq; bA=bq; WB=Wk; bB=bk; }
    else                { WA=Wv; bA=bv; WB=Ws; bB=bs; }

    int t  = threadIdx.x;
    int r0 = blockIdx.x*64;

    #pragma unroll
    for (int i = 0; i < 16; i++){
        int idx = t + i*128;
        int k = idx >> 5, c4 = idx & 31;
        float4 w = (c4 < 16) ? ((const float4*)WA)[k*16 + c4]
                             : ((const float4*)WB)[k*16 + (c4-16)];
        ((float4*)Wsh)[k*32 + c4] = w;
    }
    #pragma unroll
    for (int i = 0; i < 8; i++){
        int idx = t + i*128;
        int row = idx >> 4, c4 = idx & 15;
        float4 xv = make_float4(0.f,0.f,0.f,0.f);
        if (r0 + row < n) xv = ((const float4*)X)[(size_t)(r0+row)*16 + c4];
        int k0 = c4*4;
        Xs[(k0+0)*64 + (row ^ (((k0+0)&7)*8))] = xv.x;
        Xs[(k0+1)*64 + (row ^ (((k0+1)&7)*8))] = xv.y;
        Xs[(k0+2)*64 + (row ^ (((k0+2)&7)*8))] = xv.z;
        Xs[(k0+3)*64 + (row ^ (((k0+3)&7)*8))] = xv.w;
    }
    __syncthreads();

    int tx = t & 15, ty = t >> 4;
    int cx = tx*8, ry = ty*8;

    unsigned long long acc[8][4];
    #pragma unroll
    for (int r = 0; r < 8; r++)
        #pragma unroll
        for (int c = 0; c < 4; c++) acc[r][c] = 0ull;

    #pragma unroll 8
    for (int k = 0; k < 64; k++){
        int sw = (k & 7)*8;
        const float* ap = &Xs[k*64 + (ry ^ sw)];
        float4 a0 = *(const float4*)ap;
        float4 a1 = *(const float4*)(ap + 4);
        ulonglong2 b01 = *(const ulonglong2*)&Wsh[k*128 + cx];
        ulonglong2 b23 = *(const ulonglong2*)&Wsh[k*128 + cx + 4];
        unsigned long long bp0 = b01.x, bp1 = b01.y, bp2 = b23.x, bp3 = b23.y;
        float av[8] = {a0.x,a0.y,a0.z,a0.w,a1.x,a1.y,a1.z,a1.w};
        #pragma unroll
        for (int r = 0; r < 8; r++){
            unsigned long long ap2;
            asm("mov.b64 %0, {%1,%1};" : "=l"(ap2) : "f"(av[r]));
            asm("fma.rn.f32x2 %0, %1, %2, %0;" : "+l"(acc[r][0]) : "l"(ap2), "l"(bp0));
            asm("fma.rn.f32x2 %0, %1, %2, %0;" : "+l"(acc[r][1]) : "l"(ap2), "l"(bp1));
            asm("fma.rn.f32x2 %0, %1, %2, %0;" : "+l"(acc[r][2]) : "l"(ap2), "l"(bp2));
            asm("fma.rn.f32x2 %0, %1, %2, %0;" : "+l"(acc[r][3]) : "l"(ap2), "l"(bp3));
        }
    }

    // output routing
    const float* bias; int cc = (cx < 64) ? cx : cx - 64;
    float* Yf = nullptr; __half* Yh = nullptr;
    if (blockIdx.y == 0){
        if (cx < 64){ Yf = g_q;  bias = bA; }
        else        { Yh = g_kh; bias = bB; }
    } else {
        if (cx < 64){ Yh = g_vh; bias = bA; }
        else        { Yf = g_s;  bias = bB; }
    }
    float bv8[8];
    #pragma unroll
    for (int j = 0; j < 8; j++) bv8[j] = bias[cc + j];
    // residual only into the skip output (g_s)
    bool res = (addres != 0) && (blockIdx.y == 1) && (cx >= 64);

    #pragma unroll
    for (int r = 0; r < 8; r++){
        int row = ry + r;
        if (r0 + row >= n) continue;
        float o[8];
        #pragma unroll
        for (int c = 0; c < 4; c++){
            float lo, hi;
            asm("mov.b64 {%0,%1}, %2;" : "=f"(lo), "=f"(hi) : "l"(acc[r][c]));
            o[2*c]   = lo + bv8[2*c];
            o[2*c+1] = hi + bv8[2*c+1];
        }
        if (res){
            #pragma unroll
            for (int j = 0; j < 8; j++){
                int c = cc + j;
                o[j] += Xs[c*64 + (row ^ ((c & 7)*8))];
            }
        }
        if (Yh){
            __half2 hh[4];
            #pragma unroll
            for (int c = 0; c < 4; c++)
                hh[c] = __floats2half2_rn(o[2*c], o[2*c+1]);
            *(uint4*)(&Yh[(size_t)(r0+row)*64 + cc]) = *(uint4*)hh;
        } else {
            ((float4*)Yf)[(size_t)(r0+row)*16 + (cc>>2)]     = make_float4(o[0],o[1],o[2],o[3]);
            ((float4*)Yf)[(size_t)(r0+row)*16 + (cc>>2) + 1] = make_float4(o[4],o[5],o[6],o[7]);
        }
    }
}

// ------- fused per-node attention, D=64, half k/v --------------------------
// 16 lanes per node; lane owns k-cols [lane*4, lane*4+3].
__device__ __forceinline__ float dot4h(const float4& q, uint2 kraw){
    __half2 h01 = *(__half2*)&kraw.x;
    __half2 h23 = *(__half2*)&kraw.y;
    float2 f01 = __half22float2(h01);
    float2 f23 = __half22float2(h23);
    return q.x*f01.x + q.y*f01.y + q.z*f23.x + q.w*f23.y;
}
__device__ __forceinline__ void accv(float4& acc, float e, uint2 vraw){
    __half2 h01 = *(__half2*)&vraw.x;
    __half2 h23 = *(__half2*)&vraw.y;
    float2 f01 = __half22float2(h01);
    float2 f23 = __half22float2(h23);
    acc.x += e*f01.x; acc.y += e*f01.y; acc.z += e*f23.x; acc.w += e*f23.y;
}

__global__ void __launch_bounds__(256) edge64(){
    int gid = blockIdx.x*16 + (threadIdx.x >> 4);
    if (gid >= NN) return;
    int lane = threadIdx.x & 15;
    unsigned gmask = 0xffffu << (threadIdx.x & 16);

    const uint2* KP = (const uint2*)g_kh;   // node*16 + lane -> 8B (4 halves)
    const uint2* VP = (const uint2*)g_vh;

    float4 q = ((const float4*)g_q)[(size_t)gid*16 + lane];
    int beg = g_ptr[gid], end = g_ptr[gid+1];

    float4 acc = make_float4(0.f,0.f,0.f,0.f);
    float ssum = 0.f;
    int i = beg;
    for (; i + 4 <= end; i += 4){
        int s0 = g_esrc[i],   s1 = g_esrc[i+1];
        int s2 = g_esrc[i+2], s3 = g_esrc[i+3];
        uint2 k0 = KP[(size_t)s0*16 + lane];
        uint2 k1 = KP[(size_t)s1*16 + lane];
        uint2 k2 = KP[(size_t)s2*16 + lane];
        uint2 k3 = KP[(size_t)s3*16 + lane];
        uint2 v0 = VP[(size_t)s0*16 + lane];
        uint2 v1 = VP[(size_t)s1*16 + lane];
        uint2 v2 = VP[(size_t)s2*16 + lane];
        uint2 v3 = VP[(size_t)s3*16 + lane];
        float d0 = dot4h(q, k0), d1 = dot4h(q, k1);
        float d2 = dot4h(q, k2), d3 = dot4h(q, k3);
        #pragma unroll
        for (int o = 8; o >= 1; o >>= 1){
            d0 += __shfl_xor_sync(gmask, d0, o);
            d1 += __shfl_xor_sync(gmask, d1, o);
            d2 += __shfl_xor_sync(gmask, d2, o);
            d3 += __shfl_xor_sync(gmask, d3, o);
        }
        float e0 = __expf(d0*0.125f);
        float e1 = __expf(d1*0.125f);
        float e2 = __expf(d2*0.125f);
        float e3 = __expf(d3*0.125f);
        ssum += (e0 + e1) + (e2 + e3);
        accv(acc, e0, v0); accv(acc, e1, v1);
        accv(acc, e2, v2); accv(acc, e3, v3);
    }
    for (; i < end; i++){
        int s0 = g_esrc[i];
        uint2 k0 = KP[(size_t)s0*16 + lane];
        uint2 v0 = VP[(size_t)s0*16 + lane];
        float d0 = dot4h(q, k0);
        #pragma unroll
        for (int o = 8; o >= 1; o >>= 1)
            d0 += __shfl_xor_sync(gmask, d0, o);
        float e0 = __expf(d0*0.125f);
        ssum += e0;
        accv(acc, e0, v0);
    }
    float inv = 1.0f / (ssum + 1e-16f);
    float4 sk = ((const float4*)g_s)[(size_t)gid*16 + lane];
    float4 o;
    o.x = tanhf(acc.x*inv + sk.x);
    o.y = tanhf(acc.y*inv + sk.y);
    o.z = tanhf(acc.z*inv + sk.z);
    o.w = tanhf(acc.w*inv + sk.w);
    ((float4*)g_h)[(size_t)gid*16 + lane] = o;
}

// ---------------- layer 3: 64 -> (3 x 4) GEMM, packed kv ----------------
__global__ void __launch_bounds__(256) gemm3(
    const float* __restrict__ X,
    const float* __restrict__ Wq, const float* __restrict__ bq,
    const float* __restrict__ Wk, const float* __restrict__ bk,
    const float* __restrict__ Wv, const float* __restrict__ bv,
    const float* __restrict__ Ws, const float* __restrict__ bs,
    const float* __restrict__ noise, int n)
{
    __shared__ float w[64*12];
    __shared__ float bias[12];
    int t = threadIdx.x;
    if (t < 192){
        int kk = t/3, j = t%3;
        w[kk*12 + 0 + j] = Wq[t];
        w[kk*12 + 3 + j] = Wk[t];
        w[kk*12 + 6 + j] = Wv[t];
        w[kk*12 + 9 + j] = Ws[t];
    }
    if (t < 3){
        bias[t]   = bq[t];
        bias[3+t] = bk[t];
        bias[6+t] = bv[t];
        bias[9+t] = bs[t];
    }
    __syncthreads();
    int node = blockIdx.x*256 + t;
    if (node >= n) return;
    float acc[12];
    #pragma unroll
    for (int j = 0; j < 12; j++) acc[j] = 0.f;
    #pragma unroll
    for (int kk = 0; kk < 16; kk++){
        float4 xv = ((const float4*)X)[(size_t)node*16 + kk];
        #pragma unroll
        for (int j = 0; j < 12; j++){
            acc[j] += xv.x * w[(kk*4+0)*12+j]
                    + xv.y * w[(kk*4+1)*12+j]
                    + xv.z * w[(kk*4+2)*12+j]
                    + xv.w * w[(kk*4+3)*12+j];
        }
    }
    float4 q3 = make_float4(acc[0]+bias[0], acc[1]+bias[1], acc[2]+bias[2], 0.f);
    // packed kv: {kx,ky,kz,vx, vy,vz,0,0}
    float4 kva = make_float4(acc[3]+bias[3], acc[4]+bias[4], acc[5]+bias[5],
                             acc[6]+bias[6]);
    float4 kvb = make_float4(acc[7]+bias[7], acc[8]+bias[8], 0.f, 0.f);
    float4 s3 = make_float4(acc[9]+bias[9]   + 0.1f*noise[node*3+0],
                            acc[10]+bias[10] + 0.1f*noise[node*3+1],
                            acc[11]+bias[11] + 0.1f*noise[node*3+2], 0.f);
    ((float4*)g_q3)[node] = q3;
    ((float4*)g_kv3)[node*2]   = kva;
    ((float4*)g_kv3)[node*2+1] = kvb;
    ((float4*)g_s3)[node] = s3;
}

// ------- layer-3 fused per-node attention (C=3), thread per node -------
__global__ void __launch_bounds__(256) edge3(float* __restrict__ out){
    int node = blockIdx.x*256 + threadIdx.x;
    if (node >= NN) return;
    float4 q = ((const float4*)g_q3)[node];
    int beg = g_ptr[node], end = g_ptr[node+1];
    float sum = 0.f, ax = 0.f, ay = 0.f, az = 0.f;
    int i = beg;
    for (; i + 2 <= end; i += 2){
        int s0 = g_esrc[i], s1 = g_esrc[i+1];
        float4 a0 = ((const float4*)g_kv3)[s0*2];
        float4 b0 = ((const float4*)g_kv3)[s0*2+1];
        float4 a1 = ((const float4*)g_kv3)[s1*2];
        float4 b1 = ((const float4*)g_kv3)[s1*2+1];
        float e0 = __expf((q.x*a0.x + q.y*a0.y + q.z*a0.z)*0.57735026919f);
        float e1 = __expf((q.x*a1.x + q.y*a1.y + q.z*a1.z)*0.57735026919f);
        sum += e0 + e1;
        ax += e0*a0.w + e1*a1.w;
        ay += e0*b0.x + e1*b1.x;
        az += e0*b0.y + e1*b1.y;
    }
    if (i < end){
        int s0 = g_esrc[i];
        float4 a0 = ((const float4*)g_kv3)[s0*2];
        float4 b0 = ((const float4*)g_kv3)[s0*2+1];
        float e0 = __expf((q.x*a0.x + q.y*a0.y + q.z*a0.z)*0.57735026919f);
        sum += e0;
        ax += e0*a0.w; ay += e0*b0.x; az += e0*b0.y;
    }
    float inv = 1.0f / (sum + 1e-16f);
    float4 s3 = ((const float4*)g_s3)[node];
    out[node*3+0] = ax*inv + s3.x;
    out[node*3+1] = ay*inv + s3.y;
    out[node*3+2] = az*inv + s3.z;
}

// ---------------- launcher ----------------
extern "C" void kernel_launch(void* const* d_in, const int* in_sizes, int n_in,
                              void* d_out, int out_size)
{
    const float* x     = (const float*)d_in[0];
    const int*   ei    = (const int*)d_in[1];
    const float* noise = (const float*)d_in[2];
    const float* p[24];
    for (int i = 0; i < 24; i++) p[i] = (const float*)d_in[3+i];
    float* out = (float*)d_out;

    float* hptr = nullptr;
    cudaGetSymbolAddress((void**)&hptr, g_h);
    int* degptr = nullptr;
    cudaGetSymbolAddress((void**)&degptr, g_deg);

    int eb4 = (NE/4 + 255)/256;
    int nb  = (NN + 255)/256;
    dim3 gg((NN + 63)/64, 2);
    int ng  = (NN + 15)/16;

    // CSR build (reused by all layers)
    cudaMemsetAsync(degptr, 0, NN*sizeof(int));
    hist_k<<<eb4,256>>>(ei);
    scan_k<<<1,1024>>>();
    scatter_k<<<eb4,256>>>(ei);

    // layer 1
    gemm4<<<gg,128>>>(x, p[0],p[1],p[2],p[3],p[4],p[5],p[6],p[7], NN, 0);
    edge64<<<ng,256>>>();

    // layer 2 (residual folded into skip output)
    gemm4<<<gg,128>>>(hptr, p[8],p[9],p[10],p[11],p[12],p[13],p[14],p[15], NN, 1);
    edge64<<<ng,256>>>();

    // layer 3
    gemm3<<<nb,256>>>(hptr, p[16],p[17],p[18],p[19],p[20],p[21],p[22],p[23],
                      noise, NN);
    edge3<<<nb,256>>>(out);
}

// round 5
// speedup vs baseline: 2.3458x; 1.0370x over previous
#include <cuda_runtime.h>
#include <cuda_fp16.h>
#include <math.h>

#define NN 100000
#define NE 3200000

// ---------------- scratch (device globals) ----------------
__device__ __align__(16) float  g_q [NN*64];
__device__ __align__(16) __half g_kh[NN*64];
__device__ __align__(16) __half g_vh[NN*64];
__device__ __align__(16) float  g_s [NN*64];   // skip (x@Ws+b [+residual])
__device__ __align__(16) float  g_h [NN*64];   // layer output
__device__ __align__(16) float  g_q3 [NN*4];
__device__ __align__(16) float  g_s3 [NN*4];   // skip3 + 0.1*noise
__device__ __align__(32) float  g_kv3[NN*8];   // {k3.xyz, v3.x, v3.yz, pad2}
__device__ int g_deg[NN];
__device__ int g_ptr[NN+1];
__device__ int g_cur[NN];
__device__ int g_esrc[NE];

// ---------------- CSR build ----------------
__global__ void hist_k(const int* __restrict__ ei){
    int i = blockIdx.x*blockDim.x + threadIdx.x;   // NE/4 threads
    if (i < NE/4){
        int4 d = ((const int4*)(ei + NE))[i];
        atomicAdd(&g_deg[d.x], 1);
        atomicAdd(&g_deg[d.y], 1);
        atomicAdd(&g_deg[d.z], 1);
        atomicAdd(&g_deg[d.w], 1);
    }
}
__global__ void __launch_bounds__(1024) scan_k(){
    __shared__ int sh[1024];
    int t = threadIdx.x;
    int carry = 0;
    for (int base = 0; base < NN; base += 4096){
        int v[4]; int s = 0;
        #pragma unroll
        for (int j = 0; j < 4; j++){
            int idx = base + t*4 + j;
            v[j] = (idx < NN) ? g_deg[idx] : 0;
            s += v[j];
        }
        sh[t] = s; __syncthreads();
        #pragma unroll
        for (int off = 1; off < 1024; off <<= 1){
            int x = (t >= off) ? sh[t-off] : 0;
            __syncthreads();
            sh[t] += x;
            __syncthreads();
        }
        int total = sh[1023];
        int excl = carry + sh[t] - s;
        #pragma unroll
        for (int j = 0; j < 4; j++){
            int idx = base + t*4 + j;
            if (idx < NN){ g_ptr[idx] = excl; g_cur[idx] = excl; }
            excl += v[j];
        }
        carry += total;
        __syncthreads();
    }
    if (t == 0) g_ptr[NN] = carry;
}
__global__ void scatter_k(const int* __restrict__ ei){
    int i = blockIdx.x*blockDim.x + threadIdx.x;   // NE/4 threads
    if (i < NE/4){
        int4 s = ((const int4*)ei)[i];
        int4 d = ((const int4*)(ei + NE))[i];
        g_esrc[atomicAdd(&g_cur[d.x], 1)] = s.x;
        g_esrc[atomicAdd(&g_cur[d.y], 1)] = s.y;
        g_esrc[atomicAdd(&g_cur[d.z], 1)] = s.z;
        g_esrc[atomicAdd(&g_cur[d.w], 1)] = s.w;
    }
}

// ---------------- fused dual GEMM: Y[N,64] = X@W + b for two W's ----------
// blockIdx.y==0 -> (Wq->g_q fp32, Wk->g_kh half)
// blockIdx.y==1 -> (Wv->g_vh half, Ws->g_s fp32)
// Each thread: 8 rows x (4 cols of matrix A + 4 cols of matrix B).
// W reads are 16B-stride contiguous across lanes -> conflict-free LDS.
__global__ void __launch_bounds__(128) gemm4(
    const float* __restrict__ X,
    const float* __restrict__ Wq, const float* __restrict__ bq,
    const float* __restrict__ Wk, const float* __restrict__ bk,
    const float* __restrict__ Wv, const float* __restrict__ bv,
    const float* __restrict__ Ws, const float* __restrict__ bs,
    int n, int addres)
{
    __shared__ float Xs[64*64];    // transposed + swizzled: [k][row^((k&7)*8)]
    __shared__ float Wsh[64*128];  // [k][c] c: 0..63 matrix A, 64..127 matrix B

    const float* WA; const float* WB; const float* bA; const float* bB;
    if (blockIdx.y == 0){ WA=Wq; bA=bq; WB=Wk; bB=bk; }
    else                { WA=Wv; bA=bv; WB=Ws; bB=bs; }

    int t  = threadIdx.x;
    int r0 = blockIdx.x*64;

    #pragma unroll
    for (int i = 0; i < 16; i++){
        int idx = t + i*128;
        int k = idx >> 5, c4 = idx & 31;
        float4 w = (c4 < 16) ? ((const float4*)WA)[k*16 + c4]
                             : ((const float4*)WB)[k*16 + (c4-16)];
        ((float4*)Wsh)[k*32 + c4] = w;
    }
    #pragma unroll
    for (int i = 0; i < 8; i++){
        int idx = t + i*128;
        int row = idx >> 4, c4 = idx & 15;
        float4 xv = make_float4(0.f,0.f,0.f,0.f);
        if (r0 + row < n) xv = ((const float4*)X)[(size_t)(r0+row)*16 + c4];
        int k0 = c4*4;
        Xs[(k0+0)*64 + (row ^ (((k0+0)&7)*8))] = xv.x;
        Xs[(k0+1)*64 + (row ^ (((k0+1)&7)*8))] = xv.y;
        Xs[(k0+2)*64 + (row ^ (((k0+2)&7)*8))] = xv.z;
        Xs[(k0+3)*64 + (row ^ (((k0+3)&7)*8))] = xv.w;
    }
    __syncthreads();

    int tx = t & 15, ty = t >> 4;
    int c  = tx*4;          // col quad (same index into matrix A and B halves)
    int ry = ty*8;

    // acc[r][0..1] = matrix A cols c..c+3 ; acc[r][2..3] = matrix B cols c..c+3
    unsigned long long acc[8][4];
    #pragma unroll
    for (int r = 0; r < 8; r++)
        #pragma unroll
        for (int q = 0; q < 4; q++) acc[r][q] = 0ull;

    #pragma unroll 8
    for (int k = 0; k < 64; k++){
        int sw = (k & 7)*8;
        const float* ap = &Xs[k*64 + (ry ^ sw)];
        float4 a0 = *(const float4*)ap;
        float4 a1 = *(const float4*)(ap + 4);
        ulonglong2 wA = *(const ulonglong2*)&Wsh[k*128 + c];        // conflict-free
        ulonglong2 wB = *(const ulonglong2*)&Wsh[k*128 + 64 + c];   // conflict-free
        float av[8] = {a0.x,a0.y,a0.z,a0.w,a1.x,a1.y,a1.z,a1.w};
        #pragma unroll
        for (int r = 0; r < 8; r++){
            unsigned long long ap2;
            asm("mov.b64 %0, {%1,%1};" : "=l"(ap2) : "f"(av[r]));
            asm("fma.rn.f32x2 %0, %1, %2, %0;" : "+l"(acc[r][0]) : "l"(ap2), "l"(wA.x));
            asm("fma.rn.f32x2 %0, %1, %2, %0;" : "+l"(acc[r][1]) : "l"(ap2), "l"(wA.y));
            asm("fma.rn.f32x2 %0, %1, %2, %0;" : "+l"(acc[r][2]) : "l"(ap2), "l"(wB.x));
            asm("fma.rn.f32x2 %0, %1, %2, %0;" : "+l"(acc[r][3]) : "l"(ap2), "l"(wB.y));
        }
    }

    // routing: A quad, B quad
    float* YfA = nullptr; __half* YhA = nullptr;
    float* YfB = nullptr; __half* YhB = nullptr;
    if (blockIdx.y == 0){ YfA = g_q;  YhB = g_kh; }
    else                { YhA = g_vh; YfB = g_s;  }
    float bA4[4], bB4[4];
    #pragma unroll
    for (int j = 0; j < 4; j++){ bA4[j] = bA[c+j]; bB4[j] = bB[c+j]; }
    bool res = (addres != 0) && (blockIdx.y == 1);   // residual -> g_s (B quad)

    #pragma unroll
    for (int r = 0; r < 8; r++){
        int row = ry + r;
        if (r0 + row >= n) continue;
        float oA[4], oB[4];
        #pragma unroll
        for (int q = 0; q < 2; q++){
            float lo, hi;
            asm("mov.b64 {%0,%1}, %2;" : "=f"(lo), "=f"(hi) : "l"(acc[r][q]));
            oA[2*q] = lo + bA4[2*q]; oA[2*q+1] = hi + bA4[2*q+1];
            asm("mov.b64 {%0,%1}, %2;" : "=f"(lo), "=f"(hi) : "l"(acc[r][q+2]));
            oB[2*q] = lo + bB4[2*q]; oB[2*q+1] = hi + bB4[2*q+1];
        }
        if (res){
            #pragma unroll
            for (int j = 0; j < 4; j++){
                int cc = c + j;
                oB[j] += Xs[cc*64 + (row ^ ((cc & 7)*8))];
            }
        }
        if (YfA){
            ((float4*)YfA)[(size_t)(r0+row)*16 + (c>>2)] = make_float4(oA[0],oA[1],oA[2],oA[3]);
        } else {
            __half2 h0 = __floats2half2_rn(oA[0], oA[1]);
            __half2 h1 = __floats2half2_rn(oA[2], oA[3]);
            uint2 u; *(__half2*)&u.x = h0; *(__half2*)&u.y = h1;
            *(uint2*)&YhA[(size_t)(r0+row)*64 + c] = u;
        }
        if (YfB){
            ((float4*)YfB)[(size_t)(r0+row)*16 + (c>>2)] = make_float4(oB[0],oB[1],oB[2],oB[3]);
        } else {
            __half2 h0 = __floats2half2_rn(oB[0], oB[1]);
            __half2 h1 = __floats2half2_rn(oB[2], oB[3]);
            uint2 u; *(__half2*)&u.x = h0; *(__half2*)&u.y = h1;
            *(uint2*)&YhB[(size_t)(r0+row)*64 + c] = u;
        }
    }
}

// ------- fused per-node attention, D=64, half k/v --------------------------
__device__ __forceinline__ float dot4h(const float4& q, uint2 kraw){
    __half2 h01 = *(__half2*)&kraw.x;
    __half2 h23 = *(__half2*)&kraw.y;
    float2 f01 = __half22float2(h01);
    float2 f23 = __half22float2(h23);
    return q.x*f01.x + q.y*f01.y + q.z*f23.x + q.w*f23.y;
}
__device__ __forceinline__ void accv(float4& acc, float e, uint2 vraw){
    __half2 h01 = *(__half2*)&vraw.x;
    __half2 h23 = *(__half2*)&vraw.y;
    float2 f01 = __half22float2(h01);
    float2 f23 = __half22float2(h23);
    acc.x += e*f01.x; acc.y += e*f01.y; acc.z += e*f23.x; acc.w += e*f23.y;
}

__global__ void __launch_bounds__(256) edge64(){
    int gid = blockIdx.x*16 + (threadIdx.x >> 4);
    if (gid >= NN) return;
    int lane = threadIdx.x & 15;
    unsigned gmask = 0xffffu << (threadIdx.x & 16);

    const uint2* KP = (const uint2*)g_kh;
    const uint2* VP = (const uint2*)g_vh;

    float4 q = ((const float4*)g_q)[(size_t)gid*16 + lane];
    int beg = g_ptr[gid], end = g_ptr[gid+1];

    float4 acc = make_float4(0.f,0.f,0.f,0.f);
    float ssum = 0.f;
    int i = beg;
    for (; i + 4 <= end; i += 4){
        int s0 = g_esrc[i],   s1 = g_esrc[i+1];
        int s2 = g_esrc[i+2], s3 = g_esrc[i+3];
        uint2 k0 = KP[(size_t)s0*16 + lane];
        uint2 k1 = KP[(size_t)s1*16 + lane];
        uint2 k2 = KP[(size_t)s2*16 + lane];
        uint2 k3 = KP[(size_t)s3*16 + lane];
        uint2 v0 = VP[(size_t)s0*16 + lane];
        uint2 v1 = VP[(size_t)s1*16 + lane];
        uint2 v2 = VP[(size_t)s2*16 + lane];
        uint2 v3 = VP[(size_t)s3*16 + lane];
        float d0 = dot4h(q, k0), d1 = dot4h(q, k1);
        float d2 = dot4h(q, k2), d3 = dot4h(q, k3);
        #pragma unroll
        for (int o = 8; o >= 1; o >>= 1){
            d0 += __shfl_xor_sync(gmask, d0, o);
            d1 += __shfl_xor_sync(gmask, d1, o);
            d2 += __shfl_xor_sync(gmask, d2, o);
            d3 += __shfl_xor_sync(gmask, d3, o);
        }
        float e0 = __expf(d0*0.125f);
        float e1 = __expf(d1*0.125f);
        float e2 = __expf(d2*0.125f);
        float e3 = __expf(d3*0.125f);
        ssum += (e0 + e1) + (e2 + e3);
        accv(acc, e0, v0); accv(acc, e1, v1);
        accv(acc, e2, v2); accv(acc, e3, v3);
    }
    for (; i < end; i++){
        int s0 = g_esrc[i];
        uint2 k0 = KP[(size_t)s0*16 + lane];
        uint2 v0 = VP[(size_t)s0*16 + lane];
        float d0 = dot4h(q, k0);
        #pragma unroll
        for (int o = 8; o >= 1; o >>= 1)
            d0 += __shfl_xor_sync(gmask, d0, o);
        float e0 = __expf(d0*0.125f);
        ssum += e0;
        accv(acc, e0, v0);
    }
    float inv = 1.0f / (ssum + 1e-16f);
    float4 sk = ((const float4*)g_s)[(size_t)gid*16 + lane];
    float4 o;
    o.x = tanhf(acc.x*inv + sk.x);
    o.y = tanhf(acc.y*inv + sk.y);
    o.z = tanhf(acc.z*inv + sk.z);
    o.w = tanhf(acc.w*inv + sk.w);
    ((float4*)g_h)[(size_t)gid*16 + lane] = o;
}

// ---------------- layer 3: 64 -> (3 x 4) GEMM, packed kv ----------------
__global__ void __launch_bounds__(256) gemm3(
    const float* __restrict__ X,
    const float* __restrict__ Wq, const float* __restrict__ bq,
    const float* __restrict__ Wk, const float* __restrict__ bk,
    const float* __restrict__ Wv, const float* __restrict__ bv,
    const float* __restrict__ Ws, const float* __restrict__ bs,
    const float* __restrict__ noise, int n)
{
    __shared__ float w[64*12];
    __shared__ float bias[12];
    int t = threadIdx.x;
    if (t < 192){
        int kk = t/3, j = t%3;
        w[kk*12 + 0 + j] = Wq[t];
        w[kk*12 + 3 + j] = Wk[t];
        w[kk*12 + 6 + j] = Wv[t];
        w[kk*12 + 9 + j] = Ws[t];
    }
    if (t < 3){
        bias[t]   = bq[t];
        bias[3+t] = bk[t];
        bias[6+t] = bv[t];
        bias[9+t] = bs[t];
    }
    __syncthreads();
    int node = blockIdx.x*256 + t;
    if (node >= n) return;
    float acc[12];
    #pragma unroll
    for (int j = 0; j < 12; j++) acc[j] = 0.f;
    #pragma unroll
    for (int kk = 0; kk < 16; kk++){
        float4 xv = ((const float4*)X)[(size_t)node*16 + kk];
        #pragma unroll
        for (int j = 0; j < 12; j++){
            acc[j] += xv.x * w[(kk*4+0)*12+j]
                    + xv.y * w[(kk*4+1)*12+j]
                    + xv.z * w[(kk*4+2)*12+j]
                    + xv.w * w[(kk*4+3)*12+j];
        }
    }
    float4 q3 = make_float4(acc[0]+bias[0], acc[1]+bias[1], acc[2]+bias[2], 0.f);
    float4 kva = make_float4(acc[3]+bias[3], acc[4]+bias[4], acc[5]+bias[5],
                             acc[6]+bias[6]);
    float4 kvb = make_float4(acc[7]+bias[7], acc[8]+bias[8], 0.f, 0.f);
    float4 s3 = make_float4(acc[9]+bias[9]   + 0.1f*noise[node*3+0],
                            acc[10]+bias[10] + 0.1f*noise[node*3+1],
                            acc[11]+bias[11] + 0.1f*noise[node*3+2], 0.f);
    ((float4*)g_q3)[node] = q3;
    ((float4*)g_kv3)[node*2]   = kva;
    ((float4*)g_kv3)[node*2+1] = kvb;
    ((float4*)g_s3)[node] = s3;
}

// ------- layer-3 fused per-node attention (C=3), thread per node -------
__global__ void __launch_bounds__(256) edge3(float* __restrict__ out){
    int node = blockIdx.x*256 + threadIdx.x;
    if (node >= NN) return;
    float4 q = ((const float4*)g_q3)[node];
    int beg = g_ptr[node], end = g_ptr[node+1];
    float sum = 0.f, ax = 0.f, ay = 0.f, az = 0.f;
    int i = beg;
    for (; i + 2 <= end; i += 2){
        int s0 = g_esrc[i], s1 = g_esrc[i+1];
        float4 a0 = ((const float4*)g_kv3)[s0*2];
        float4 b0 = ((const float4*)g_kv3)[s0*2+1];
        float4 a1 = ((const float4*)g_kv3)[s1*2];
        float4 b1 = ((const float4*)g_kv3)[s1*2+1];
        float e0 = __expf((q.x*a0.x + q.y*a0.y + q.z*a0.z)*0.57735026919f);
        float e1 = __expf((q.x*a1.x + q.y*a1.y + q.z*a1.z)*0.57735026919f);
        sum += e0 + e1;
        ax += e0*a0.w + e1*a1.w;
        ay += e0*b0.x + e1*b1.x;
        az += e0*b0.y + e1*b1.y;
    }
    if (i < end){
        int s0 = g_esrc[i];
        float4 a0 = ((const float4*)g_kv3)[s0*2];
        float4 b0 = ((const float4*)g_kv3)[s0*2+1];
        float e0 = __expf((q.x*a0.x + q.y*a0.y + q.z*a0.z)*0.57735026919f);
        sum += e0;
        ax += e0*a0.w; ay += e0*b0.x; az += e0*b0.y;
    }
    float inv = 1.0f / (sum + 1e-16f);
    float4 s3 = ((const float4*)g_s3)[node];
    out[node*3+0] = ax*inv + s3.x;
    out[node*3+1] = ay*inv + s3.y;
    out[node*3+2] = az*inv + s3.z;
}

// ---------------- launcher ----------------
extern "C" void kernel_launch(void* const* d_in, const int* in_sizes, int n_in,
                              void* d_out, int out_size)
{
    const float* x     = (const float*)d_in[0];
    const int*   ei    = (const int*)d_in[1];
    const float* noise = (const float*)d_in[2];
    const float* p[24];
    for (int i = 0; i < 24; i++) p[i] = (const float*)d_in[3+i];
    float* out = (float*)d_out;

    float* hptr = nullptr;
    cudaGetSymbolAddress((void**)&hptr, g_h);
    int* degptr = nullptr;
    cudaGetSymbolAddress((void**)&degptr, g_deg);

    // one-time side stream + events (host objects; no device allocation).
    // Work enqueued is identical on every call — deterministic.
    static cudaStream_t s_csr = nullptr;
    static cudaEvent_t ev_fork = nullptr, ev_csr = nullptr;
    if (!s_csr){
        cudaStreamCreateWithFlags(&s_csr, cudaStreamNonBlocking);
        cudaEventCreateWithFlags(&ev_fork, cudaEventDisableTiming);
        cudaEventCreateWithFlags(&ev_csr,  cudaEventDisableTiming);
    }

    int eb4 = (NE/4 + 255)/256;
    int nb  = (NN + 255)/256;
    dim3 gg((NN + 63)/64, 2);
    int ng  = (NN + 15)/16;

    // ---- fork: CSR build on side stream, concurrent with layer-1 GEMM ----
    cudaEventRecord(ev_fork, 0);
    cudaStreamWaitEvent(s_csr, ev_fork, 0);
    cudaMemsetAsync(degptr, 0, NN*sizeof(int), s_csr);
    hist_k<<<eb4,256,0,s_csr>>>(ei);
    scan_k<<<1,1024,0,s_csr>>>();
    scatter_k<<<eb4,256,0,s_csr>>>(ei);
    cudaEventRecord(ev_csr, s_csr);

    // layer-1 GEMM on main stream (independent of CSR)
    gemm4<<<gg,128>>>(x, p[0],p[1],p[2],p[3],p[4],p[5],p[6],p[7], NN, 0);

    // join: edge64 needs both GEMM outputs and CSR
    cudaStreamWaitEvent(0, ev_csr, 0);
    edge64<<<ng,256>>>();

    // layer 2 (residual folded into skip output)
    gemm4<<<gg,128>>>(hptr, p[8],p[9],p[10],p[11],p[12],p[13],p[14],p[15], NN, 1);
    edge64<<<ng,256>>>();

    // layer 3
    gemm3<<<nb,256>>>(hptr, p[16],p[17],p[18],p[19],p[20],p[21],p[22],p[23],
                      noise, NN);
    edge3<<<nb,256>>>(out);
}

// round 6
// speedup vs baseline: 2.3779x; 1.0137x over previous
#include <cuda_runtime.h>
#include <cuda_fp16.h>
#include <math.h>

#define NN 100000
#define NE 3200000
#define CH0 50048              // chunk-0 rows (multiple of 64 and of 16)

// ---------------- scratch (device globals) ----------------
// q / kv / s are double-buffered (ping-pong between layers) so layer-(i+1)
// GEMM writes can overlap layer-i edge gathers without WAR hazards.
__device__ __align__(16) float g_q [2*NN*64];
__device__ __align__(16) uint4 g_kvh[2*NN*16];   // per node,lane: {k0..3,v0..3} fp16
__device__ __align__(16) float g_s [2*NN*64];
__device__ __align__(16) float g_h [NN*64];
__device__ __align__(16) float g_q3 [NN*4];
__device__ __align__(16) float g_s3 [NN*4];
__device__ __align__(32) float g_kv3[NN*8];
__device__ int g_deg[NN];
__device__ int g_ptr[NN+1];
__device__ int g_cur[NN];
__device__ int g_esrc[NE];

// ---------------- CSR build ----------------
__global__ void hist_k(const int* __restrict__ ei){
    int i = blockIdx.x*blockDim.x + threadIdx.x;
    if (i < NE/4){
        int4 d = ((const int4*)(ei + NE))[i];
        atomicAdd(&g_deg[d.x], 1);
        atomicAdd(&g_deg[d.y], 1);
        atomicAdd(&g_deg[d.z], 1);
        atomicAdd(&g_deg[d.w], 1);
    }
}
__global__ void __launch_bounds__(1024) scan_k(){
    __shared__ int sh[1024];
    int t = threadIdx.x;
    int carry = 0;
    for (int base = 0; base < NN; base += 4096){
        int v[4]; int s = 0;
        #pragma unroll
        for (int j = 0; j < 4; j++){
            int idx = base + t*4 + j;
            v[j] = (idx < NN) ? g_deg[idx] : 0;
            s += v[j];
        }
        sh[t] = s; __syncthreads();
        #pragma unroll
        for (int off = 1; off < 1024; off <<= 1){
            int x = (t >= off) ? sh[t-off] : 0;
            __syncthreads();
            sh[t] += x;
            __syncthreads();
        }
        int total = sh[1023];
        int excl = carry + sh[t] - s;
        #pragma unroll
        for (int j = 0; j < 4; j++){
            int idx = base + t*4 + j;
            if (idx < NN){ g_ptr[idx] = excl; g_cur[idx] = excl; }
            excl += v[j];
        }
        carry += total;
        __syncthreads();
    }
    if (t == 0) g_ptr[NN] = carry;
}
__global__ void scatter_k(const int* __restrict__ ei){
    int i = blockIdx.x*blockDim.x + threadIdx.x;
    if (i < NE/4){
        int4 s = ((const int4*)ei)[i];
        int4 d = ((const int4*)(ei + NE))[i];
        g_esrc[atomicAdd(&g_cur[d.x], 1)] = s.x;
        g_esrc[atomicAdd(&g_cur[d.y], 1)] = s.y;
        g_esrc[atomicAdd(&g_cur[d.z], 1)] = s.z;
        g_esrc[atomicAdd(&g_cur[d.w], 1)] = s.w;
    }
}

// ---------------- fused dual GEMM over row range [row0, min(row0+?,NN)) ----
// blockIdx.y==0 -> (Wq -> q fp32, Wk -> kv.k fp16)
// blockIdx.y==1 -> (Wv -> kv.v fp16, Ws -> s fp32 [+residual])
__global__ void __launch_bounds__(128) gemm4(
    const float* __restrict__ X,
    const float* __restrict__ Wq, const float* __restrict__ bq,
    const float* __restrict__ Wk, const float* __restrict__ bk,
    const float* __restrict__ Wv, const float* __restrict__ bv,
    const float* __restrict__ Ws, const float* __restrict__ bs,
    int row0, int buf, int addres)
{
    __shared__ float Xs[64*64];
    __shared__ float Wsh[64*128];

    const float* WA; const float* WB; const float* bA; const float* bB;
    if (blockIdx.y == 0){ WA=Wq; bA=bq; WB=Wk; bB=bk; }
    else                { WA=Wv; bA=bv; WB=Ws; bB=bs; }

    int t  = threadIdx.x;
    int r0 = row0 + blockIdx.x*64;

    float* Q  = g_q + (size_t)buf*NN*64;
    float* S  = g_s + (size_t)buf*NN*64;
    uint4* KV = g_kvh + (size_t)buf*NN*16;

    #pragma unroll
    for (int i = 0; i < 16; i++){
        int idx = t + i*128;
        int k = idx >> 5, c4 = idx & 31;
        float4 w = (c4 < 16) ? ((const float4*)WA)[k*16 + c4]
                             : ((const float4*)WB)[k*16 + (c4-16)];
        ((float4*)Wsh)[k*32 + c4] = w;
    }
    #pragma unroll
    for (int i = 0; i < 8; i++){
        int idx = t + i*128;
        int row = idx >> 4, c4 = idx & 15;
        float4 xv = make_float4(0.f,0.f,0.f,0.f);
        if (r0 + row < NN) xv = ((const float4*)X)[(size_t)(r0+row)*16 + c4];
        int k0 = c4*4;
        Xs[(k0+0)*64 + (row ^ (((k0+0)&7)*8))] = xv.x;
        Xs[(k0+1)*64 + (row ^ (((k0+1)&7)*8))] = xv.y;
        Xs[(k0+2)*64 + (row ^ (((k0+2)&7)*8))] = xv.z;
        Xs[(k0+3)*64 + (row ^ (((k0+3)&7)*8))] = xv.w;
    }
    __syncthreads();

    int tx = t & 15, ty = t >> 4;
    int c  = tx*4;
    int ry = ty*8;

    unsigned long long acc[8][4];
    #pragma unroll
    for (int r = 0; r < 8; r++)
        #pragma unroll
        for (int q = 0; q < 4; q++) acc[r][q] = 0ull;

    #pragma unroll 8
    for (int k = 0; k < 64; k++){
        int sw = (k & 7)*8;
        const float* ap = &Xs[k*64 + (ry ^ sw)];
        float4 a0 = *(const float4*)ap;
        float4 a1 = *(const float4*)(ap + 4);
        ulonglong2 wA = *(const ulonglong2*)&Wsh[k*128 + c];
        ulonglong2 wB = *(const ulonglong2*)&Wsh[k*128 + 64 + c];
        float av[8] = {a0.x,a0.y,a0.z,a0.w,a1.x,a1.y,a1.z,a1.w};
        #pragma unroll
        for (int r = 0; r < 8; r++){
            unsigned long long ap2;
            asm("mov.b64 %0, {%1,%1};" : "=l"(ap2) : "f"(av[r]));
            asm("fma.rn.f32x2 %0, %1, %2, %0;" : "+l"(acc[r][0]) : "l"(ap2), "l"(wA.x));
            asm("fma.rn.f32x2 %0, %1, %2, %0;" : "+l"(acc[r][1]) : "l"(ap2), "l"(wA.y));
            asm("fma.rn.f32x2 %0, %1, %2, %0;" : "+l"(acc[r][2]) : "l"(ap2), "l"(wB.x));
            asm("fma.rn.f32x2 %0, %1, %2, %0;" : "+l"(acc[r][3]) : "l"(ap2), "l"(wB.y));
        }
    }

    float bA4[4], bB4[4];
    #pragma unroll
    for (int j = 0; j < 4; j++){ bA4[j] = bA[c+j]; bB4[j] = bB[c+j]; }
    bool res = (addres != 0) && (blockIdx.y == 1);   // residual -> s only

    #pragma unroll
    for (int r = 0; r < 8; r++){
        int row = ry + r;
        if (r0 + row >= NN) continue;
        float oA[4], oB[4];
        #pragma unroll
        for (int q = 0; q < 2; q++){
            float lo, hi;
            asm("mov.b64 {%0,%1}, %2;" : "=f"(lo), "=f"(hi) : "l"(acc[r][q]));
            oA[2*q] = lo + bA4[2*q]; oA[2*q+1] = hi + bA4[2*q+1];
            asm("mov.b64 {%0,%1}, %2;" : "=f"(lo), "=f"(hi) : "l"(acc[r][q+2]));
            oB[2*q] = lo + bB4[2*q]; oB[2*q+1] = hi + bB4[2*q+1];
        }
        if (res){
            #pragma unroll
            for (int j = 0; j < 4; j++){
                int cc = c + j;
                oB[j] += Xs[cc*64 + (row ^ ((cc & 7)*8))];
            }
        }
        size_t grow = (size_t)(r0+row);
        uint2* kvslot = (uint2*)&KV[grow*16 + tx];
        if (blockIdx.y == 0){
            ((float4*)Q)[grow*16 + tx] = make_float4(oA[0],oA[1],oA[2],oA[3]);
            __half2 h0 = __floats2half2_rn(oB[0], oB[1]);
            __half2 h1 = __floats2half2_rn(oB[2], oB[3]);
            uint2 u; *(__half2*)&u.x = h0; *(__half2*)&u.y = h1;
            kvslot[0] = u;                               // k slot
        } else {
            __half2 h0 = __floats2half2_rn(oA[0], oA[1]);
            __half2 h1 = __floats2half2_rn(oA[2], oA[3]);
            uint2 u; *(__half2*)&u.x = h0; *(__half2*)&u.y = h1;
            kvslot[1] = u;                               // v slot
            ((float4*)S)[grow*16 + tx] = make_float4(oB[0],oB[1],oB[2],oB[3]);
        }
    }
}

// ------- fused per-node attention, D=64, interleaved fp16 kv ---------------
__device__ __forceinline__ float dot4h(const float4& q, unsigned a, unsigned b){
    float2 f01 = __half22float2(*(__half2*)&a);
    float2 f23 = __half22float2(*(__half2*)&b);
    return q.x*f01.x + q.y*f01.y + q.z*f23.x + q.w*f23.y;
}
__device__ __forceinline__ void accv(float4& acc, float e, unsigned a, unsigned b){
    float2 f01 = __half22float2(*(__half2*)&a);
    float2 f23 = __half22float2(*(__half2*)&b);
    acc.x += e*f01.x; acc.y += e*f01.y; acc.z += e*f23.x; acc.w += e*f23.y;
}

__global__ void __launch_bounds__(256) edge64(int buf, int base, int nnodes){
    int lid = blockIdx.x*16 + (threadIdx.x >> 4);
    if (lid >= nnodes) return;
    int gid = base + lid;
    int lane = threadIdx.x & 15;
    unsigned gmask = 0xffffu << (threadIdx.x & 16);

    const float* Q  = g_q + (size_t)buf*NN*64;
    const float* S  = g_s + (size_t)buf*NN*64;
    const uint4* KV = g_kvh + (size_t)buf*NN*16;

    float4 q = ((const float4*)Q)[(size_t)gid*16 + lane];
    int beg = g_ptr[gid], end = g_ptr[gid+1];

    float4 acc = make_float4(0.f,0.f,0.f,0.f);
    float ssum = 0.f;
    int i = beg;
    for (; i + 4 <= end; i += 4){
        int s0 = g_esrc[i],   s1 = g_esrc[i+1];
        int s2 = g_esrc[i+2], s3 = g_esrc[i+3];
        uint4 kv0 = KV[(size_t)s0*16 + lane];
        uint4 kv1 = KV[(size_t)s1*16 + lane];
        uint4 kv2 = KV[(size_t)s2*16 + lane];
        uint4 kv3 = KV[(size_t)s3*16 + lane];
        float d0 = dot4h(q, kv0.x, kv0.y);
        float d1 = dot4h(q, kv1.x, kv1.y);
        float d2 = dot4h(q, kv2.x, kv2.y);
        float d3 = dot4h(q, kv3.x, kv3.y);
        #pragma unroll
        for (int o = 8; o >= 1; o >>= 1){
            d0 += __shfl_xor_sync(gmask, d0, o);
            d1 += __shfl_xor_sync(gmask, d1, o);
            d2 += __shfl_xor_sync(gmask, d2, o);
            d3 += __shfl_xor_sync(gmask, d3, o);
        }
        float e0 = __expf(d0*0.125f);
        float e1 = __expf(d1*0.125f);
        float e2 = __expf(d2*0.125f);
        float e3 = __expf(d3*0.125f);
        ssum += (e0 + e1) + (e2 + e3);
        accv(acc, e0, kv0.z, kv0.w); accv(acc, e1, kv1.z, kv1.w);
        accv(acc, e2, kv2.z, kv2.w); accv(acc, e3, kv3.z, kv3.w);
    }
    for (; i < end; i++){
        int s0 = g_esrc[i];
        uint4 kv0 = KV[(size_t)s0*16 + lane];
        float d0 = dot4h(q, kv0.x, kv0.y);
        #pragma unroll
        for (int o = 8; o >= 1; o >>= 1)
            d0 += __shfl_xor_sync(gmask, d0, o);
        float e0 = __expf(d0*0.125f);
        ssum += e0;
        accv(acc, e0, kv0.z, kv0.w);
    }
    float inv = 1.0f / (ssum + 1e-16f);
    float4 sk = ((const float4*)S)[(size_t)gid*16 + lane];
    float4 o;
    o.x = tanhf(acc.x*inv + sk.x);
    o.y = tanhf(acc.y*inv + sk.y);
    o.z = tanhf(acc.z*inv + sk.z);
    o.w = tanhf(acc.w*inv + sk.w);
    ((float4*)g_h)[(size_t)gid*16 + lane] = o;
}

// ---------------- layer 3: 64 -> (3 x 4) GEMM over row range ----------------
__global__ void __launch_bounds__(256) gemm3(
    const float* __restrict__ X,
    const float* __restrict__ Wq, const float* __restrict__ bq,
    const float* __restrict__ Wk, const float* __restrict__ bk,
    const float* __restrict__ Wv, const float* __restrict__ bv,
    const float* __restrict__ Ws, const float* __restrict__ bs,
    const float* __restrict__ noise, int row0)
{
    __shared__ float w[64*12];
    __shared__ float bias[12];
    int t = threadIdx.x;
    if (t < 192){
        int kk = t/3, j = t%3;
        w[kk*12 + 0 + j] = Wq[t];
        w[kk*12 + 3 + j] = Wk[t];
        w[kk*12 + 6 + j] = Wv[t];
        w[kk*12 + 9 + j] = Ws[t];
    }
    if (t < 3){
        bias[t]   = bq[t];
        bias[3+t] = bk[t];
        bias[6+t] = bv[t];
        bias[9+t] = bs[t];
    }
    __syncthreads();
    int node = row0 + blockIdx.x*256 + t;
    if (node >= NN) return;
    float acc[12];
    #pragma unroll
    for (int j = 0; j < 12; j++) acc[j] = 0.f;
    #pragma unroll
    for (int kk = 0; kk < 16; kk++){
        float4 xv = ((const float4*)X)[(size_t)node*16 + kk];
        #pragma unroll
        for (int j = 0; j < 12; j++){
            acc[j] += xv.x * w[(kk*4+0)*12+j]
                    + xv.y * w[(kk*4+1)*12+j]
                    + xv.z * w[(kk*4+2)*12+j]
                    + xv.w * w[(kk*4+3)*12+j];
        }
    }
    float4 q3 = make_float4(acc[0]+bias[0], acc[1]+bias[1], acc[2]+bias[2], 0.f);
    float4 kva = make_float4(acc[3]+bias[3], acc[4]+bias[4], acc[5]+bias[5],
                             acc[6]+bias[6]);
    float4 kvb = make_float4(acc[7]+bias[7], acc[8]+bias[8], 0.f, 0.f);
    float4 s3 = make_float4(acc[9]+bias[9]   + 0.1f*noise[node*3+0],
                            acc[10]+bias[10] + 0.1f*noise[node*3+1],
                            acc[11]+bias[11] + 0.1f*noise[node*3+2], 0.f);
    ((float4*)g_q3)[node] = q3;
    ((float4*)g_kv3)[node*2]   = kva;
    ((float4*)g_kv3)[node*2+1] = kvb;
    ((float4*)g_s3)[node] = s3;
}

// ------- layer-3 fused per-node attention (C=3), thread per node -------
__global__ void __launch_bounds__(256) edge3(float* __restrict__ out){
    int node = blockIdx.x*256 + threadIdx.x;
    if (node >= NN) return;
    float4 q = ((const float4*)g_q3)[node];
    int beg = g_ptr[node], end = g_ptr[node+1];
    float sum = 0.f, ax = 0.f, ay = 0.f, az = 0.f;
    int i = beg;
    for (; i + 2 <= end; i += 2){
        int s0 = g_esrc[i], s1 = g_esrc[i+1];
        float4 a0 = ((const float4*)g_kv3)[s0*2];
        float4 b0 = ((const float4*)g_kv3)[s0*2+1];
        float4 a1 = ((const float4*)g_kv3)[s1*2];
        float4 b1 = ((const float4*)g_kv3)[s1*2+1];
        float e0 = __expf((q.x*a0.x + q.y*a0.y + q.z*a0.z)*0.57735026919f);
        float e1 = __expf((q.x*a1.x + q.y*a1.y + q.z*a1.z)*0.57735026919f);
        sum += e0 + e1;
        ax += e0*a0.w + e1*a1.w;
        ay += e0*b0.x + e1*b1.x;
        az += e0*b0.y + e1*b1.y;
    }
    if (i < end){
        int s0 = g_esrc[i];
        float4 a0 = ((const float4*)g_kv3)[s0*2];
        float4 b0 = ((const float4*)g_kv3)[s0*2+1];
        float e0 = __expf((q.x*a0.x + q.y*a0.y + q.z*a0.z)*0.57735026919f);
        sum += e0;
        ax += e0*a0.w; ay += e0*b0.x; az += e0*b0.y;
    }
    float inv = 1.0f / (sum + 1e-16f);
    float4 s3 = ((const float4*)g_s3)[node];
    out[node*3+0] = ax*inv + s3.x;
    out[node*3+1] = ay*inv + s3.y;
    out[node*3+2] = az*inv + s3.z;
}

// ---------------- launcher ----------------
extern "C" void kernel_launch(void* const* d_in, const int* in_sizes, int n_in,
                              void* d_out, int out_size)
{
    const float* x     = (const float*)d_in[0];
    const int*   ei    = (const int*)d_in[1];
    const float* noise = (const float*)d_in[2];
    const float* p[24];
    for (int i = 0; i < 24; i++) p[i] = (const float*)d_in[3+i];
    float* out = (float*)d_out;

    float* hptr = nullptr;
    cudaGetSymbolAddress((void**)&hptr, g_h);
    int* degptr = nullptr;
    cudaGetSymbolAddress((void**)&degptr, g_deg);

    static cudaStream_t s2 = nullptr;
    static cudaEvent_t ev_fork = nullptr, ev_csr = nullptr,
                       ev_e1a = nullptr, ev_g2a = nullptr,
                       ev_e2a = nullptr, ev_g3a = nullptr;
    if (!s2){
        cudaStreamCreateWithFlags(&s2, cudaStreamNonBlocking);
        cudaEventCreateWithFlags(&ev_fork, cudaEventDisableTiming);
        cudaEventCreateWithFlags(&ev_csr,  cudaEventDisableTiming);
        cudaEventCreateWithFlags(&ev_e1a,  cudaEventDisableTiming);
        cudaEventCreateWithFlags(&ev_g2a,  cudaEventDisableTiming);
        cudaEventCreateWithFlags(&ev_e2a,  cudaEventDisableTiming);
        cudaEventCreateWithFlags(&ev_g3a,  cudaEventDisableTiming);
    }

    int eb4 = (NE/4 + 255)/256;
    int nb  = (NN + 255)/256;
    const int CH1 = NN - CH0;
    dim3 gg_full((NN + 63)/64, 2);
    dim3 gg_a(CH0/64, 2);                 // 782
    dim3 gg_b((CH1 + 63)/64, 2);          // 781
    int ng_a = CH0/16, ng_b = CH1/16;     // 3128, 3122
    int nb3_a = (CH0 + 255)/256, nb3_b = (CH1 + 255)/256;

    // ---- CSR build on side stream, overlapped with layer-1 GEMM ----
    cudaEventRecord(ev_fork, 0);
    cudaStreamWaitEvent(s2, ev_fork, 0);
    cudaMemsetAsync(degptr, 0, NN*sizeof(int), s2);
    hist_k<<<eb4,256,0,s2>>>(ei);
    scan_k<<<1,1024,0,s2>>>();
    scatter_k<<<eb4,256,0,s2>>>(ei);
    cudaEventRecord(ev_csr, s2);

    // layer-1 GEMM (full, buf 0)
    gemm4<<<gg_full,128>>>(x, p[0],p[1],p[2],p[3],p[4],p[5],p[6],p[7], 0, 0, 0);

    // layer-1 edges, chunked; layer-2 GEMM chunk-a overlaps chunk-b edges
    cudaStreamWaitEvent(0, ev_csr, 0);
    edge64<<<ng_a,256>>>(0, 0, CH0);
    cudaEventRecord(ev_e1a, 0);
    edge64<<<ng_b,256>>>(0, CH0, CH1);

    cudaStreamWaitEvent(s2, ev_e1a, 0);
    gemm4<<<gg_a,128,0,s2>>>(hptr, p[8],p[9],p[10],p[11],p[12],p[13],p[14],p[15],
                             0, 1, 1);
    cudaEventRecord(ev_g2a, s2);

    gemm4<<<gg_b,128>>>(hptr, p[8],p[9],p[10],p[11],p[12],p[13],p[14],p[15],
                        CH0, 1, 1);
    cudaStreamWaitEvent(0, ev_g2a, 0);

    // layer-2 edges, chunked; layer-3 GEMM chunk-a overlaps chunk-b edges
    edge64<<<ng_a,256>>>(1, 0, CH0);
    cudaEventRecord(ev_e2a, 0);
    edge64<<<ng_b,256>>>(1, CH0, CH1);

    cudaStreamWaitEvent(s2, ev_e2a, 0);
    gemm3<<<nb3_a,256,0,s2>>>(hptr, p[16],p[17],p[18],p[19],p[20],p[21],p[22],p[23],
                              noise, 0);
    cudaEventRecord(ev_g3a, s2);

    gemm3<<<nb3_b,256>>>(hptr, p[16],p[17],p[18],p[19],p[20],p[21],p[22],p[23],
                         noise, CH0);
    cudaStreamWaitEvent(0, ev_g3a, 0);
    edge3<<<nb,256>>>(out);
}